// round 7
// baseline (speedup 1.0000x reference)
#include <cuda_runtime.h>
#include <cstdint>

#define MAXB 16
#define MAXN 24564
#define MAXC 81
#define CAP  1024      // per-(b,c) candidate shortlist capacity
#define KPC  50        // MAX_PER_CLASS
#define MAXTOT 200
#define THETA 0.98f    // shortlist score threshold ( > SCORE_THR=0.5 )
#define TH2   0.995f   // tier-1 selection threshold inside shortlist
#define SELB  256      // phaseB tier-1 selection capacity (pow2)
#define SELC  512      // phaseC selection capacity (pow2)
#define NBIN  512
#define ATILE 64       // anchors per phaseA pipeline stage
#define ANIT  4        // tiles per phaseA block

typedef unsigned long long ull;

// ---------------- static device scratch ----------------
__device__ float4 g_boxes[MAXB * MAXN];
__device__ unsigned char g_mask[MAXB * MAXN];
__device__ ull g_cand[(size_t)MAXB * MAXC * CAP];
__device__ int g_candCnt[MAXB * MAXC];
__device__ float g_keptScore[MAXB * MAXC * KPC];
__device__ int   g_keptN[MAXB * MAXC * KPC];

__device__ __forceinline__ float iouf(float4 a, float4 b) {
    float iy1 = fmaxf(a.x, b.x);
    float ix1 = fmaxf(a.y, b.y);
    float iy2 = fminf(a.z, b.z);
    float ix2 = fminf(a.w, b.w);
    float inter = fmaxf(iy2 - iy1, 0.f) * fmaxf(ix2 - ix1, 0.f);
    float a0 = (a.z - a.x) * (a.w - a.y);
    float a1 = (b.z - b.x) * (b.w - b.y);
    return inter / (a0 + a1 - inter + 1e-8f);
}

__device__ __forceinline__ void bitonic_desc(ull* a, int P, int tid, int nthreads) {
    for (int k = 2; k <= P; k <<= 1) {
        for (int j = k >> 1; j > 0; j >>= 1) {
            for (int i = tid; i < P; i += nthreads) {
                int ixj = i ^ j;
                if (ixj > i) {
                    ull x = a[i], y = a[ixj];
                    if (((i & k) != 0) ? (x > y) : (x < y)) { a[i] = y; a[ixj] = x; }
                }
            }
            __syncthreads();
        }
    }
}

__device__ __forceinline__ void cp_async16(uint32_t saddr, const void* gaddr) {
    asm volatile("cp.async.cg.shared.global [%0], [%1], 16;" :: "r"(saddr), "l"(gaddr));
}
__device__ __forceinline__ void cp_commit() {
    asm volatile("cp.async.commit_group;");
}
template <int W> __device__ __forceinline__ void cp_wait() {
    asm volatile("cp.async.wait_group %0;" :: "n"(W));
}

// ---------------- Phase A v6: 4 lanes/anchor, static-smem cp.async pipeline ----
__global__ __launch_bounds__(256) void phaseA(
    const float* __restrict__ labels,   // (B,N,C)
    const float* __restrict__ deltas,   // (B,N,4)
    const float* __restrict__ priors,   // (N,4)
    int N, int C)
{
    __shared__ __align__(16) float sL[2][ATILE * MAXC];   // 2 x 20.7 KB

    int tid = threadIdx.x;
    int b = blockIdx.y;
    int blk0 = blockIdx.x * (ATILE * ANIT);
    int nAll = min(ATILE * ANIT, N - blk0);
    if (nAll <= 0) return;
    int nt = (nAll + ATILE - 1) / ATILE;
    size_t bBase = (size_t)b * N;

    // --- decode all anchors of this block (independent of labels) ---
    for (int i = tid; i < nAll; i += 256) {
        int n = blk0 + i;
        float4 pr = ((const float4*)priors)[n];
        float4 dd = ((const float4*)deltas)[bBase + n];
        float ph = pr.z - pr.x, pw = pr.w - pr.y;
        float pcy = pr.x + 0.5f * ph, pcx = pr.y + 0.5f * pw;
        float d0 = dd.x * 0.1f, d1 = dd.y * 0.1f;
        float d2 = dd.z * 0.2f, d3 = dd.w * 0.2f;
        float cy = d0 * ph + pcy, cx = d1 * pw + pcx;
        float h = expf(d2) * ph, w = expf(d3) * pw;
        float4 bx;
        bx.x = fminf(fmaxf(cy - h * 0.5f, 0.f), 1.f);
        bx.y = fminf(fmaxf(cx - w * 0.5f, 0.f), 1.f);
        bx.z = fminf(fmaxf(cy + h * 0.5f, 0.f), 1.f);
        bx.w = fminf(fmaxf(cx + w * 0.5f, 0.f), 1.f);
        g_boxes[bBase + n] = bx;
    }

    const float* gtile0 = labels + (bBase + blk0) * (size_t)C;
    bool aligned = ((((uintptr_t)gtile0) & 15) == 0);

    // prefetch tile 0
    {
        int naT = min(ATILE, nAll);
        int totF = naT * C;
        if (aligned) {
            uint32_t s = (uint32_t)__cvta_generic_to_shared(sL[0]);
            int tot4 = totF >> 2;
            for (int i = tid; i < tot4; i += 256)
                cp_async16(s + i * 16, (const float4*)gtile0 + i);
            for (int i = (tot4 << 2) + tid; i < totF; i += 256) sL[0][i] = gtile0[i];
        } else {
            for (int i = tid; i < totF; i += 256) sL[0][i] = gtile0[i];
        }
        cp_commit();
    }

    int a4 = tid >> 2;                 // anchor-in-tile 0..63
    int q  = tid & 3;                  // quarter within anchor
    int start = q * 20 + (q != 0);     // class range start: {0,21,41,61}
    int len   = (q == 0) ? 21 : 20;
    int laneBase = (tid & 31) & ~3;    // nibble base lane (for v0 broadcast)

    for (int t = 0; t < nt; t++) {
        // prefetch tile t+1 into the other buffer
        if (t + 1 < nt) {
            int naT = min(ATILE, nAll - (t + 1) * ATILE);
            int totF = naT * C;
            const float* g = gtile0 + (size_t)(t + 1) * ATILE * C;
            float* sb = sL[(t + 1) & 1];
            if (aligned) {
                uint32_t s = (uint32_t)__cvta_generic_to_shared(sb);
                int tot4 = totF >> 2;
                for (int i = tid; i < tot4; i += 256)
                    cp_async16(s + i * 16, (const float4*)g + i);
                for (int i = (tot4 << 2) + tid; i < totF; i += 256) sb[i] = g[i];
            } else {
                for (int i = tid; i < totF; i += 256) sb[i] = g[i];
            }
            cp_commit();
            cp_wait<1>();
        } else {
            cp_wait<0>();
        }
        __syncthreads();

        // --- compute tile t ---
        const float* buf = sL[t & 1];
        int naT = min(ATILE, nAll - t * ATILE);
        bool valid = (a4 < naT);
        const float* row = buf + (valid ? a4 : 0) * C;

        float v0 = (q == 0) ? row[0] : -1e30f;
        float m = -1e30f;
        unsigned cb = 0;
        #pragma unroll
        for (int i = 0; i < 21; i++) {
            if (i < len) {
                int c = start + i;
                float v = row[c];
                m = fmaxf(m, (c == 0) ? -1e30f : v);
                if (v > THETA) cb |= (1u << i);
            }
        }
        // combine max over the 4 lanes of this anchor
        m = fmaxf(m, __shfl_xor_sync(0xffffffffu, m, 1));
        m = fmaxf(m, __shfl_xor_sync(0xffffffffu, m, 2));
        v0 = __shfl_sync(0xffffffffu, v0, laneBase);
        bool mask = (m > v0);          // argmax != 0 (first-index tie-break)

        if (valid) {
            int n = blk0 + t * ATILE + a4;
            if (q == 0) g_mask[bBase + n] = (unsigned char)mask;
            if (mask && cb) {
                unsigned tail = 0xFFFFFFFFu - (unsigned)n;
                while (cb) {
                    int k = __ffs(cb) - 1; cb &= cb - 1;
                    int c = start + k;
                    float v = row[c];
                    int col = b * C + c;
                    int p = atomicAdd(&g_candCnt[col], 1);
                    if (p < CAP)
                        g_cand[(size_t)col * CAP + p] =
                            ((ull)__float_as_uint(v) << 32) | (ull)tail;
                }
            }
        }
        __syncthreads();   // buffer consumed before t+2 overwrites it
    }
}

// warp-0 sequential greedy scan over a descending-sorted array. Returns kept.
__device__ __forceinline__ int nms_scan(
    const ull* arr, int n, const float4* candBox, int prefN,
    size_t bBase, int lane,
    float4* keptBox, float* keptS, int* keptNi)
{
    int kept = 0;
    for (int i = 0; i < n && kept < KPC; i++) {
        ull kk = arr[i];
        unsigned nn = 0xFFFFFFFFu - (unsigned)(kk & 0xFFFFFFFFull);
        float4 bb = (i < prefN) ? candBox[i] : g_boxes[bBase + nn];
        bool sup = false;
        for (int t = lane; t < kept; t += 32)
            if (iouf(keptBox[t], bb) > 0.5f) sup = true;
        if (__any_sync(0xffffffffu, sup)) continue;
        if (lane == 0) {
            keptBox[kept] = bb;
            keptS[kept] = __uint_as_float((unsigned)(kk >> 32));
            keptNi[kept] = (int)nn;
        }
        kept++;
        __syncwarp();
    }
    return kept;
}

// ---------------- Phase B: per-(b,c) tier-1 sorted-scan NMS (+exact fallback) ----
__global__ __launch_bounds__(128) void phaseB(
    const float* __restrict__ labels, int B, int N, int C)
{
    int col = blockIdx.x;                 // b*C + c
    int b = col / C, c = col - b * C;
    int tid = threadIdx.x, lane = tid & 31, wid = tid >> 5;

    __shared__ ull sel[SELB];
    __shared__ float4 candBox[SELB];
    __shared__ float4 keptBox[KPC];
    __shared__ float keptS[KPC];
    __shared__ int keptNi[KPC];
    __shared__ int s_selCnt, s_kept, s_t3;
    __shared__ ull s_wmax[4];
    __shared__ ull s_best;

    int rawCnt = g_candCnt[col];
    int cnt = min(rawCnt, CAP);
    size_t bBase = (size_t)b * N;

    if (tid == 0) { s_selCnt = 0; s_t3 = 0; s_kept = 0; }
    __syncthreads();

    // ---- tier 1: select keys >= TH2 straight from global, sort, scan ----
    const ull T2 = ((ull)__float_as_uint(TH2)) << 32;
    const ull* gsrc = g_cand + (size_t)col * CAP;
    for (int i = tid; i < cnt; i += 128) {
        ull k = gsrc[i];
        if (k >= T2) {
            int p = atomicAdd(&s_selCnt, 1);
            if (p < SELB) sel[p] = k;
        }
    }
    __syncthreads();
    int selCnt = s_selCnt;
    bool t1ok = (selCnt <= SELB);
    int m = min(selCnt, SELB);

    if (t1ok) {
        for (int i = tid; i < SELB; i += 128)
            if (i >= m) sel[i] = 0ull;
        __syncthreads();
        bitonic_desc(sel, SELB, tid, 128);
        for (int i = tid; i < m; i += 128) {
            unsigned nn = 0xFFFFFFFFu - (unsigned)(sel[i] & 0xFFFFFFFFull);
            candBox[i] = g_boxes[bBase + nn];
        }
        __syncthreads();
        if (wid == 0) {
            int kept = nms_scan(sel, m, candBox, m, bBase, lane, keptBox, keptS, keptNi);
            if (lane == 0) {
                s_kept = kept;
                s_t3 = (kept < KPC && m < cnt);   // tier-1 prefix insufficient
            }
        }
    } else {
        if (tid == 0) s_t3 = 1;                   // selection overflow
    }
    __syncthreads();

    if (tid == 0) s_t3 = s_t3 || (rawCnt > CAP) || (s_kept < KPC);
    __syncthreads();

    // ---- tier 3: exact repeated-argmax greedy over all scores > 0.5 ----
    // (statistically never taken; guarantees exactness on any input)
    if (s_t3) {
        if (tid == 0) s_kept = 0;
        __syncthreads();
        for (int iter = 0; iter < KPC; iter++) {
            int kept = s_kept;
            ull best = 0ull;
            for (int n = tid; n < N; n += 128) {
                if (!g_mask[bBase + n]) continue;
                float s = labels[(bBase + n) * C + c];
                if (s <= 0.5f) continue;
                ull key = ((ull)__float_as_uint(s) << 32) |
                          (0xFFFFFFFFu - (unsigned)n);
                if (key <= best) continue;
                float4 bb = g_boxes[bBase + n];
                bool sup = false;
                for (int t = 0; t < kept && !sup; t++) {
                    if (keptNi[t] == n) sup = true;
                    else if (iouf(keptBox[t], bb) > 0.5f) sup = true;
                }
                if (!sup) best = key;
            }
            for (int off = 16; off; off >>= 1) {
                ull o = __shfl_xor_sync(0xffffffffu, best, off);
                if (o > best) best = o;
            }
            if (lane == 0) s_wmax[wid] = best;
            __syncthreads();
            if (wid == 0) {
                ull v = (lane < 4) ? s_wmax[lane] : 0ull;
                for (int off = 2; off; off >>= 1) {
                    ull o = __shfl_xor_sync(0xffffffffu, v, off);
                    if (o > v) v = o;
                }
                if (lane == 0) s_best = v;
            }
            __syncthreads();
            if (s_best == 0ull) break;
            if (tid == 0) {
                ull kk = s_best;
                unsigned nn = 0xFFFFFFFFu - (unsigned)(kk & 0xFFFFFFFFull);
                keptBox[s_kept] = g_boxes[bBase + nn];
                keptS[s_kept] = __uint_as_float((unsigned)(kk >> 32));
                keptNi[s_kept] = (int)nn;
                s_kept = s_kept + 1;
            }
            __syncthreads();
        }
        __syncthreads();
    }

    int kept = s_kept;
    for (int k = tid; k < KPC; k += 128) {
        g_keptScore[(size_t)col * KPC + k] = (k < kept) ? keptS[k] : 0.f;
        g_keptN   [(size_t)col * KPC + k] = (k < kept) ? keptNi[k] : 0;
    }
}

// ---------------- Phase C: histogram top-200 selection + small sort ----------------
__global__ __launch_bounds__(256) void phaseC(
    float* __restrict__ out, int B, int N, int C)
{
    int b = blockIdx.x;
    int M = C * KPC;                       // 4050
    __shared__ ull sk[4096];
    __shared__ ull sel[SELC];
    __shared__ int hist[NBIN];
    __shared__ int s_cnt, s_thr, s_fb;
    int tid = threadIdx.x;

    // reset shortlist counters for the next replay
    for (int i = tid; i < C; i += 256) g_candCnt[b * C + i] = 0;

    for (int i = tid; i < 4096; i += 256) {
        ull k = 0ull;
        if (i < M) {
            float s = g_keptScore[(size_t)b * M + i];
            k = ((ull)__float_as_uint(s) << 32) | (0xFFFFFFFFu - (unsigned)i);
        }
        sk[i] = k;
    }
    for (int i = tid; i < NBIN; i += 256) hist[i] = 0;
    if (tid == 0) { s_cnt = 0; s_thr = -1; s_fb = 0; }
    __syncthreads();

    const unsigned LOu = __float_as_uint(0.9975f);
    for (int i = tid; i < M; i += 256) {
        unsigned fb = (unsigned)(sk[i] >> 32);
        int d = (int)(fb - LOu);
        int bin = (d < 0) ? 0 : min(NBIN - 1, d >> 7);
        atomicAdd(&hist[bin], 1);
    }
    __syncthreads();

    for (int off = 1; off < NBIN; off <<= 1) {
        int v0 = hist[tid]       + ((tid + off < NBIN) ? hist[tid + off] : 0);
        int i1 = tid + 256;
        int v1 = hist[i1]        + ((i1 + off < NBIN) ? hist[i1 + off] : 0);
        __syncthreads();
        hist[tid] = v0; hist[i1] = v1;
        __syncthreads();
    }
    for (int t = tid; t < NBIN; t += 256)
        if (hist[t] >= MAXTOT && (t == NBIN - 1 || hist[t + 1] < MAXTOT)) s_thr = t;
    __syncthreads();
    int thr = s_thr;
    if (thr <= 0 || hist[thr] > SELC) { if (tid == 0) s_fb = 1; }
    __syncthreads();

    if (!s_fb) {
        for (int i = tid; i < M; i += 256) {
            unsigned fb = (unsigned)(sk[i] >> 32);
            int d = (int)(fb - LOu);
            int bin = (d < 0) ? 0 : min(NBIN - 1, d >> 7);
            if (bin >= thr) {
                int p = atomicAdd(&s_cnt, 1);
                if (p < SELC) sel[p] = sk[i];
            }
        }
        __syncthreads();
        int nsel = s_cnt;
        for (int i = tid; i < SELC; i += 256)
            if (i >= nsel) sel[i] = 0ull;
        __syncthreads();
        bitonic_desc(sel, SELC, tid, 256);
    } else {
        bitonic_desc(sk, 4096, tid, 256);
    }

    const ull* src = s_fb ? sk : sel;

    float* outBoxes   = out;
    float* outScores  = out + (size_t)B * MAXTOT * 4;
    float* outClasses = outScores + (size_t)B * MAXTOT;
    float* outCount   = outClasses + (size_t)B * MAXTOT;

    int validFlag = 0;
    if (tid < MAXTOT) {
        ull kk = src[tid];
        float s = __uint_as_float((unsigned)(kk >> 32));
        unsigned flat = 0xFFFFFFFFu - (unsigned)(kk & 0xFFFFFFFFull);
        float4 bx = make_float4(0.f, 0.f, 0.f, 0.f);
        float cls = 0.f;
        if (s > 0.f) {
            int n = g_keptN[(size_t)b * M + flat];
            bx = g_boxes[(size_t)b * N + n];
            cls = (float)(flat / KPC);
            validFlag = 1;
        }
        size_t o = (size_t)b * MAXTOT + tid;
        outBoxes[o * 4 + 0] = bx.x;
        outBoxes[o * 4 + 1] = bx.y;
        outBoxes[o * 4 + 2] = bx.z;
        outBoxes[o * 4 + 3] = bx.w;
        outScores[o]  = s;
        outClasses[o] = cls;
    }
    int vc = __syncthreads_count(validFlag);
    if (tid == 0) outCount[b] = (float)vc;
}

// ---------------- launch ----------------
extern "C" void kernel_launch(void* const* d_in, const int* in_sizes, int n_in,
                              void* d_out, int out_size) {
    const float* deltas = (const float*)d_in[0];   // pred_deltas (B,N,4)
    const float* labels = (const float*)d_in[1];   // pred_labels (B,N,C)
    const float* priors = (const float*)d_in[2];   // prior_boxes (N,4)

    int N = in_sizes[2] / 4;
    int B = in_sizes[0] / (4 * N);
    int C = in_sizes[1] / (B * N);

    dim3 gA((N + ATILE * ANIT - 1) / (ATILE * ANIT), B);
    phaseA<<<gA, 256>>>(labels, deltas, priors, N, C);
    phaseB<<<B * C, 128>>>(labels, B, N, C);
    phaseC<<<B, 256>>>((float*)d_out, B, N, C);
}

// round 8
// speedup vs baseline: 231.8924x; 231.8924x over previous
#include <cuda_runtime.h>
#include <cstdint>

#define MAXB 16
#define MAXN 24564
#define MAXC 81
#define CAP  1024      // per-(b,c) candidate shortlist capacity
#define KPC  50        // MAX_PER_CLASS
#define MAXTOT 200
#define THETA 0.98f    // shortlist score threshold ( > SCORE_THR=0.5 )
#define TH2   0.995f   // tier-1 selection threshold (classes != 0)
#define SELB  512      // phaseB tier-1 selection capacity (pow2)
#define SELC  512      // phaseC selection capacity (pow2)
#define NBIN  512
#define ATILE 64       // anchors per phaseA pipeline stage
#define ANIT  8        // tiles per phaseA block

typedef unsigned long long ull;

// ---------------- static device scratch ----------------
__device__ float4 g_boxes[MAXB * MAXN];
__device__ unsigned char g_mask[MAXB * MAXN];
__device__ ull g_cand[(size_t)MAXB * MAXC * CAP];
__device__ int g_candCnt[MAXB * MAXC];
__device__ float g_keptScore[MAXB * MAXC * KPC];
__device__ int   g_keptN[MAXB * MAXC * KPC];

__device__ __forceinline__ float iouf(float4 a, float4 b) {
    float iy1 = fmaxf(a.x, b.x);
    float ix1 = fmaxf(a.y, b.y);
    float iy2 = fminf(a.z, b.z);
    float ix2 = fminf(a.w, b.w);
    float inter = fmaxf(iy2 - iy1, 0.f) * fmaxf(ix2 - ix1, 0.f);
    float a0 = (a.z - a.x) * (a.w - a.y);
    float a1 = (b.z - b.x) * (b.w - b.y);
    return inter / (a0 + a1 - inter + 1e-8f);
}

__device__ __forceinline__ void bitonic_desc(ull* a, int P, int tid, int nthreads) {
    for (int k = 2; k <= P; k <<= 1) {
        for (int j = k >> 1; j > 0; j >>= 1) {
            for (int i = tid; i < P; i += nthreads) {
                int ixj = i ^ j;
                if (ixj > i) {
                    ull x = a[i], y = a[ixj];
                    if (((i & k) != 0) ? (x > y) : (x < y)) { a[i] = y; a[ixj] = x; }
                }
            }
            __syncthreads();
        }
    }
}

// ---- mbarrier + bulk-copy helpers ----
__device__ __forceinline__ uint32_t smem_u32(const void* p) {
    return (uint32_t)__cvta_generic_to_shared(p);
}
__device__ __forceinline__ void mbar_init(uint32_t a, uint32_t cnt) {
    asm volatile("mbarrier.init.shared.b64 [%0], %1;" :: "r"(a), "r"(cnt) : "memory");
}
__device__ __forceinline__ void mbar_expect_tx(uint32_t a, uint32_t bytes) {
    asm volatile("mbarrier.arrive.expect_tx.shared.b64 _, [%0], %1;"
                 :: "r"(a), "r"(bytes) : "memory");
}
__device__ __forceinline__ void bulk_g2s(uint32_t sdst, const void* gsrc,
                                         uint32_t bytes, uint32_t mbar) {
    asm volatile(
        "cp.async.bulk.shared::cluster.global.mbarrier::complete_tx::bytes "
        "[%0], [%1], %2, [%3];"
        :: "r"(sdst), "l"(gsrc), "r"(bytes), "r"(mbar) : "memory");
}
__device__ __forceinline__ void mbar_wait(uint32_t a, uint32_t parity) {
    asm volatile(
        "{\n\t.reg .pred p;\n\t"
        "W%=:\n\t"
        "mbarrier.try_wait.parity.acquire.cta.shared::cta.b64 p, [%0], %1, 0x989680;\n\t"
        "@!p bra W%=;\n\t}"
        :: "r"(a), "r"(parity) : "memory");
}

// ---------------- Phase A v7: bulk-copy pipeline, 4 lanes per anchor ----------------
__global__ __launch_bounds__(256) void phaseA(
    const float* __restrict__ labels,   // (B,N,C)
    const float* __restrict__ deltas,   // (B,N,4)
    const float* __restrict__ priors,   // (N,4)
    int N, int C)
{
    __shared__ __align__(16) float sL[2][ATILE * MAXC];   // 2 x 20.7 KB
    __shared__ __align__(8) ull sBar[2];

    int tid = threadIdx.x;
    int b = blockIdx.y;
    int blk0 = blockIdx.x * (ATILE * ANIT);
    int nAll = min(ATILE * ANIT, N - blk0);
    if (nAll <= 0) return;
    int nt = (nAll + ATILE - 1) / ATILE;
    size_t bBase = (size_t)b * N;

    // --- decode all anchors of this block (independent of labels) ---
    for (int i = tid; i < nAll; i += 256) {
        int n = blk0 + i;
        float4 pr = ((const float4*)priors)[n];
        float4 dd = ((const float4*)deltas)[bBase + n];
        float ph = pr.z - pr.x, pw = pr.w - pr.y;
        float pcy = pr.x + 0.5f * ph, pcx = pr.y + 0.5f * pw;
        float d0 = dd.x * 0.1f, d1 = dd.y * 0.1f;
        float d2 = dd.z * 0.2f, d3 = dd.w * 0.2f;
        float cy = d0 * ph + pcy, cx = d1 * pw + pcx;
        float h = expf(d2) * ph, w = expf(d3) * pw;
        float4 bx;
        bx.x = fminf(fmaxf(cy - h * 0.5f, 0.f), 1.f);
        bx.y = fminf(fmaxf(cx - w * 0.5f, 0.f), 1.f);
        bx.z = fminf(fmaxf(cy + h * 0.5f, 0.f), 1.f);
        bx.w = fminf(fmaxf(cx + w * 0.5f, 0.f), 1.f);
        g_boxes[bBase + n] = bx;
    }

    uint32_t bar[2] = { smem_u32(&sBar[0]), smem_u32(&sBar[1]) };
    if (tid == 0) { mbar_init(bar[0], 1); mbar_init(bar[1], 1); }
    asm volatile("fence.proxy.async.shared::cta;" ::: "memory");
    __syncthreads();

    const float* gt0 = labels + (bBase + blk0) * (size_t)C;

    // prefetch helper (inlined twice + in loop)
    auto prefetch = [&](int t) {
        int naT = min(ATILE, nAll - t * ATILE);
        uint32_t bytes = (uint32_t)naT * C * 4u;
        const float* gsrc = gt0 + (size_t)t * ATILE * C;
        float* sdst = sL[t & 1];
        bool al = ((((uintptr_t)gsrc) & 15) == 0);
        uint32_t bb = al ? (bytes & ~15u) : 0u;
        if (tid == 0) {
            mbar_expect_tx(bar[t & 1], bb);
            if (bb) bulk_g2s(smem_u32(sdst), gsrc, bb, bar[t & 1]);
        }
        // tail / fallback copied by plain threads (ordered by later __syncthreads)
        int remF = (int)((bytes - bb) >> 2);
        int baseF = (int)(bb >> 2);
        for (int i = tid; i < remF; i += 256) sdst[baseF + i] = gsrc[baseF + i];
    };

    prefetch(0);
    if (nt > 1) prefetch(1);
    __syncthreads();   // orders any scalar tail stores before first consumption

    int a4 = tid >> 2;                 // anchor-in-tile 0..63
    int q  = tid & 3;                  // quarter within anchor
    int start = q * 20 + (q != 0);     // class range start: {0,21,41,61}
    int len   = (q == 0) ? 21 : 20;
    int laneBase = (tid & 31) & ~3;

    for (int t = 0; t < nt; t++) {
        mbar_wait(bar[t & 1], (t >> 1) & 1);

        const float* buf = sL[t & 1];
        int naT = min(ATILE, nAll - t * ATILE);
        bool valid = (a4 < naT);
        const float* row = buf + (valid ? a4 : 0) * C;

        float v0 = (q == 0) ? row[0] : -1e30f;
        float m = -1e30f;
        unsigned cb = 0;
        #pragma unroll
        for (int i = 0; i < 21; i++) {
            if (i < len) {
                int c = start + i;
                float v = row[c];
                m = fmaxf(m, (c == 0) ? -1e30f : v);
                if (v > THETA) cb |= (1u << i);
            }
        }
        m = fmaxf(m, __shfl_xor_sync(0xffffffffu, m, 1));
        m = fmaxf(m, __shfl_xor_sync(0xffffffffu, m, 2));
        v0 = __shfl_sync(0xffffffffu, v0, laneBase);
        bool mask = (m > v0);          // argmax != 0 (first-index tie-break)

        if (valid) {
            int n = blk0 + t * ATILE + a4;
            if (q == 0) g_mask[bBase + n] = (unsigned char)mask;
            if (mask && cb) {
                unsigned tail = 0xFFFFFFFFu - (unsigned)n;
                while (cb) {
                    int k = __ffs(cb) - 1; cb &= cb - 1;
                    int c = start + k;
                    float v = row[c];
                    int col = b * C + c;
                    int p = atomicAdd(&g_candCnt[col], 1);
                    if (p < CAP)
                        g_cand[(size_t)col * CAP + p] =
                            ((ull)__float_as_uint(v) << 32) | (ull)tail;
                }
            }
        }
        __syncthreads();               // buffer fully consumed
        if (t + 2 < nt) prefetch(t + 2);
    }
}

// warp-0 sequential greedy scan over a descending-sorted array. Returns kept.
__device__ __forceinline__ int nms_scan(
    const ull* arr, int n, const float4* candBox, int prefN,
    size_t bBase, int lane,
    float4* keptBox, float* keptS, int* keptNi)
{
    int kept = 0;
    for (int i = 0; i < n && kept < KPC; i++) {
        ull kk = arr[i];
        unsigned nn = 0xFFFFFFFFu - (unsigned)(kk & 0xFFFFFFFFull);
        float4 bb = (i < prefN) ? candBox[i] : g_boxes[bBase + nn];
        bool sup = false;
        for (int t = lane; t < kept; t += 32)
            if (iouf(keptBox[t], bb) > 0.5f) sup = true;
        if (__any_sync(0xffffffffu, sup)) continue;
        if (lane == 0) {
            keptBox[kept] = bb;
            keptS[kept] = __uint_as_float((unsigned)(kk >> 32));
            keptNi[kept] = (int)nn;
        }
        kept++;
        __syncwarp();
    }
    return kept;
}

// ---------------- Phase B: per-(b,c) tiered sorted-scan greedy NMS ----------------
__global__ __launch_bounds__(128) void phaseB(
    const float* __restrict__ labels, int B, int N, int C)
{
    int col = blockIdx.x;                 // b*C + c
    int b = col / C, c = col - b * C;
    int tid = threadIdx.x, lane = tid & 31, wid = tid >> 5;

    __shared__ ull keys[CAP];
    __shared__ ull sel[SELB];
    __shared__ float4 candBox[256];
    __shared__ float4 keptBox[KPC];
    __shared__ float keptS[KPC];
    __shared__ int keptNi[KPC];
    __shared__ int s_selCnt, s_kept, s_t2, s_t3;
    __shared__ ull s_wmax[4];
    __shared__ ull s_best;

    int rawCnt = g_candCnt[col];
    int cnt = min(rawCnt, CAP);
    size_t bBase = (size_t)b * N;

    for (int i = tid; i < cnt; i += 128)
        keys[i] = g_cand[(size_t)col * CAP + i];
    if (tid == 0) { s_selCnt = 0; s_t2 = 0; s_t3 = 0; s_kept = 0; }
    __syncthreads();

    // ---- tier 1: class-aware selection (c==0 takes the whole shortlist) ----
    const ull T2 = (c == 0) ? 0ull : (((ull)__float_as_uint(TH2)) << 32);
    for (int i = tid; i < cnt; i += 128) {
        ull k = keys[i];
        if (k >= T2) {
            int p = atomicAdd(&s_selCnt, 1);
            if (p < SELB) sel[p] = k;
        }
    }
    __syncthreads();
    int selCnt = s_selCnt;
    bool t1ok = (selCnt <= SELB);
    int m = min(selCnt, SELB);

    if (t1ok) {
        int P = 64; while (P < m) P <<= 1;           // adaptive sort size
        for (int i = tid; i < P; i += 128)
            if (i >= m) sel[i] = 0ull;
        __syncthreads();
        bitonic_desc(sel, P, tid, 128);
        for (int i = tid; i < m && i < 256; i += 128) {
            unsigned nn = 0xFFFFFFFFu - (unsigned)(sel[i] & 0xFFFFFFFFull);
            candBox[i] = g_boxes[bBase + nn];
        }
        __syncthreads();
        if (wid == 0) {
            int kept = nms_scan(sel, m, candBox, min(m, 256), bBase, lane,
                                keptBox, keptS, keptNi);
            if (lane == 0) {
                s_kept = kept;
                s_t2 = (kept < KPC && m < cnt);      // need below-threshold keys
            }
        }
    } else {
        if (tid == 0) s_t2 = 1;                      // selection overflow
    }
    __syncthreads();

    // ---- tier 2: full bitonic over entire shortlist (rare) ----
    if (s_t2) {
        int P = 1; while (P < cnt) P <<= 1;
        if (P < 2) P = 2;
        for (int i = tid; i < P; i += 128)
            if (i >= cnt) keys[i] = 0ull;
        __syncthreads();
        bitonic_desc(keys, P, tid, 128);
        for (int i = tid; i < cnt && i < 256; i += 128) {
            unsigned nn = 0xFFFFFFFFu - (unsigned)(keys[i] & 0xFFFFFFFFull);
            candBox[i] = g_boxes[bBase + nn];
        }
        __syncthreads();
        if (wid == 0) {
            int kept = nms_scan(keys, cnt, candBox, min(cnt, 256), bBase, lane,
                                keptBox, keptS, keptNi);
            if (lane == 0) s_kept = kept;
        }
        __syncthreads();
    }

    if (tid == 0) s_t3 = (rawCnt > CAP) || (s_kept < KPC);
    __syncthreads();

    // ---- tier 3: exact repeated-argmax greedy over all scores > 0.5 ----
    // (statistically never taken; guarantees exactness on any input)
    if (s_t3) {
        if (tid == 0) s_kept = 0;
        __syncthreads();
        for (int iter = 0; iter < KPC; iter++) {
            int kept = s_kept;
            ull best = 0ull;
            for (int n = tid; n < N; n += 128) {
                if (!g_mask[bBase + n]) continue;
                float s = labels[(bBase + n) * C + c];
                if (s <= 0.5f) continue;
                ull key = ((ull)__float_as_uint(s) << 32) |
                          (0xFFFFFFFFu - (unsigned)n);
                if (key <= best) continue;
                float4 bb = g_boxes[bBase + n];
                bool sup = false;
                for (int t = 0; t < kept && !sup; t++) {
                    if (keptNi[t] == n) sup = true;
                    else if (iouf(keptBox[t], bb) > 0.5f) sup = true;
                }
                if (!sup) best = key;
            }
            for (int off = 16; off; off >>= 1) {
                ull o = __shfl_xor_sync(0xffffffffu, best, off);
                if (o > best) best = o;
            }
            if (lane == 0) s_wmax[wid] = best;
            __syncthreads();
            if (wid == 0) {
                ull v = (lane < 4) ? s_wmax[lane] : 0ull;
                for (int off = 2; off; off >>= 1) {
                    ull o = __shfl_xor_sync(0xffffffffu, v, off);
                    if (o > v) v = o;
                }
                if (lane == 0) s_best = v;
            }
            __syncthreads();
            if (s_best == 0ull) break;
            if (tid == 0) {
                ull kk = s_best;
                unsigned nn = 0xFFFFFFFFu - (unsigned)(kk & 0xFFFFFFFFull);
                keptBox[s_kept] = g_boxes[bBase + nn];
                keptS[s_kept] = __uint_as_float((unsigned)(kk >> 32));
                keptNi[s_kept] = (int)nn;
                s_kept = s_kept + 1;
            }
            __syncthreads();
        }
        __syncthreads();
    }

    int kept = s_kept;
    for (int k = tid; k < KPC; k += 128) {
        g_keptScore[(size_t)col * KPC + k] = (k < kept) ? keptS[k] : 0.f;
        g_keptN   [(size_t)col * KPC + k] = (k < kept) ? keptNi[k] : 0;
    }
}

// ---------------- Phase C: histogram top-200 selection + small sort ----------------
__global__ __launch_bounds__(256) void phaseC(
    float* __restrict__ out, int B, int N, int C)
{
    int b = blockIdx.x;
    int M = C * KPC;                       // 4050
    __shared__ ull sk[4096];
    __shared__ ull sel[SELC];
    __shared__ int hist[NBIN];
    __shared__ int s_cnt, s_thr, s_fb;
    int tid = threadIdx.x;

    // reset shortlist counters for the next replay
    for (int i = tid; i < C; i += 256) g_candCnt[b * C + i] = 0;

    for (int i = tid; i < 4096; i += 256) {
        ull k = 0ull;
        if (i < M) {
            float s = g_keptScore[(size_t)b * M + i];
            k = ((ull)__float_as_uint(s) << 32) | (0xFFFFFFFFu - (unsigned)i);
        }
        sk[i] = k;
    }
    for (int i = tid; i < NBIN; i += 256) hist[i] = 0;
    if (tid == 0) { s_cnt = 0; s_thr = -1; s_fb = 0; }
    __syncthreads();

    const unsigned LOu = __float_as_uint(0.9975f);
    for (int i = tid; i < M; i += 256) {
        unsigned fb = (unsigned)(sk[i] >> 32);
        int d = (int)(fb - LOu);
        int bin = (d < 0) ? 0 : min(NBIN - 1, d >> 7);
        atomicAdd(&hist[bin], 1);
    }
    __syncthreads();

    for (int off = 1; off < NBIN; off <<= 1) {
        int v0 = hist[tid]       + ((tid + off < NBIN) ? hist[tid + off] : 0);
        int i1 = tid + 256;
        int v1 = hist[i1]        + ((i1 + off < NBIN) ? hist[i1 + off] : 0);
        __syncthreads();
        hist[tid] = v0; hist[i1] = v1;
        __syncthreads();
    }
    for (int t = tid; t < NBIN; t += 256)
        if (hist[t] >= MAXTOT && (t == NBIN - 1 || hist[t + 1] < MAXTOT)) s_thr = t;
    __syncthreads();
    int thr = s_thr;
    if (thr <= 0 || hist[thr] > SELC) { if (tid == 0) s_fb = 1; }
    __syncthreads();

    if (!s_fb) {
        for (int i = tid; i < M; i += 256) {
            unsigned fb = (unsigned)(sk[i] >> 32);
            int d = (int)(fb - LOu);
            int bin = (d < 0) ? 0 : min(NBIN - 1, d >> 7);
            if (bin >= thr) {
                int p = atomicAdd(&s_cnt, 1);
                if (p < SELC) sel[p] = sk[i];
            }
        }
        __syncthreads();
        int nsel = s_cnt;
        for (int i = tid; i < SELC; i += 256)
            if (i >= nsel) sel[i] = 0ull;
        __syncthreads();
        bitonic_desc(sel, SELC, tid, 256);
    } else {
        bitonic_desc(sk, 4096, tid, 256);
    }

    const ull* src = s_fb ? sk : sel;

    float* outBoxes   = out;
    float* outScores  = out + (size_t)B * MAXTOT * 4;
    float* outClasses = outScores + (size_t)B * MAXTOT;
    float* outCount   = outClasses + (size_t)B * MAXTOT;

    int validFlag = 0;
    if (tid < MAXTOT) {
        ull kk = src[tid];
        float s = __uint_as_float((unsigned)(kk >> 32));
        unsigned flat = 0xFFFFFFFFu - (unsigned)(kk & 0xFFFFFFFFull);
        float4 bx = make_float4(0.f, 0.f, 0.f, 0.f);
        float cls = 0.f;
        if (s > 0.f) {
            int n = g_keptN[(size_t)b * M + flat];
            bx = g_boxes[(size_t)b * N + n];
            cls = (float)(flat / KPC);
            validFlag = 1;
        }
        size_t o = (size_t)b * MAXTOT + tid;
        outBoxes[o * 4 + 0] = bx.x;
        outBoxes[o * 4 + 1] = bx.y;
        outBoxes[o * 4 + 2] = bx.z;
        outBoxes[o * 4 + 3] = bx.w;
        outScores[o]  = s;
        outClasses[o] = cls;
    }
    int vc = __syncthreads_count(validFlag);
    if (tid == 0) outCount[b] = (float)vc;
}

// ---------------- launch ----------------
extern "C" void kernel_launch(void* const* d_in, const int* in_sizes, int n_in,
                              void* d_out, int out_size) {
    const float* deltas = (const float*)d_in[0];   // pred_deltas (B,N,4)
    const float* labels = (const float*)d_in[1];   // pred_labels (B,N,C)
    const float* priors = (const float*)d_in[2];   // prior_boxes (N,4)

    int N = in_sizes[2] / 4;
    int B = in_sizes[0] / (4 * N);
    int C = in_sizes[1] / (B * N);

    dim3 gA((N + ATILE * ANIT - 1) / (ATILE * ANIT), B);
    phaseA<<<gA, 256>>>(labels, deltas, priors, N, C);
    phaseB<<<B * C, 128>>>(labels, B, N, C);
    phaseC<<<B, 256>>>((float*)d_out, B, N, C);
}